// round 10
// baseline (speedup 1.0000x reference)
#include <cuda_runtime.h>

#define NN 1024
#define CD 256
#define HH 4
#define FF 64
#define BROWS 8
#define TMm 32
#define NSPLIT 4
#define MPS (NN / NSPLIT)      // m's per split = 256
#define NTILES (MPS / TMm)     // tiles per split = 8
#define WTS 36                 // w_t row stride (floats)

typedef unsigned long long ull;
#define ABSM 0x7FFFFFFF7FFFFFFFULL

__device__ __forceinline__ ull fma2(ull a, ull b, ull c) {
    ull d;
    asm("fma.rn.f32x2 %0, %1, %2, %3;" : "=l"(d) : "l"(a), "l"(b), "l"(c));
    return d;
}
__device__ __forceinline__ ull add2(ull a, ull b) {
    ull d;
    asm("add.rn.f32x2 %0, %1, %2;" : "=l"(d) : "l"(a), "l"(b));
    return d;
}
__device__ __forceinline__ ull pack2(float lo, float hi) {
    ull d;
    asm("mov.b64 %0, {%1, %2};" : "=l"(d) : "f"(lo), "f"(hi));
    return d;
}
__device__ __forceinline__ float2 unpack2(ull v) {
    float2 r;
    asm("mov.b64 {%0, %1}, %2;" : "=f"(r.x), "=f"(r.y) : "l"(v));
    return r;
}
__device__ __forceinline__ float hsum2(ull v) {
    float2 r = unpack2(v);
    return r.x + r.y;
}

// scratch (device globals: no allocs allowed)
__device__ float g_gl[NN * CD];
__device__ float g_gr[NN * CD];
__device__ float g_ecl[NN * HH];             // 0.6 * sum_f aw[f]*g_l[m,h,f]
__device__ float g_ecr[NN * HH];             // 0.6 * sum_f aw[f]*g_r[n,h,f]
__device__ float g_pacc[NSPLIT * NN * CD];   // partial numerators
__device__ float g_pden[NSPLIT * NN * HH];   // partial denominators

// ------- GEMM (R7 version — measured best): 32x64 tiles, 512 thr, db-buffered -------
__global__ __launch_bounds__(512)
void gemm_kernel(const float* __restrict__ X0, const float* __restrict__ W0,
                 const float* __restrict__ X1, const float* __restrict__ W1,
                 const float* __restrict__ attn_w) {
    const float* X;
    const float* W;
    float* G;
    float* EC;
    if (blockIdx.z == 0) { X = X0; W = W0; G = g_gl; EC = g_ecl; }
    else                 { X = X1; W = W1; G = g_gr; EC = g_ecr; }

    __shared__ __align__(16) float As[2][16][34];   // [buf][k][row]
    __shared__ __align__(16) float Bs[2][16][64];   // [buf][k][col]

    int t = threadIdx.x;
    int bm = blockIdx.y * 32;
    int bn = blockIdx.x * 64;
    int head = blockIdx.x;     // bn = head*64
    int tr = t >> 5;           // warp id 0..15 -> rows 2tr, 2tr+1
    int tc = t & 31;           // lane -> cols 2tc, 2tc+1

    int ar  = t >> 2;            // 0..31 (t<128)
    int ac4 = (t & 3) << 2;
    int bi  = t - 128;           // valid for t in [128,384)
    int br  = bi >> 4;
    int bc4 = (bi & 15) << 2;
    bool doA = (t < 128);
    bool doB = (t >= 128 && t < 384);

    ull acc0 = 0, acc1 = 0;

    float4 av, bv;
    if (doA) av = *(const float4*)(X + (size_t)(bm + ar) * CD + ac4);
    if (doB) bv = *(const float4*)(W + (size_t)br * CD + bn + bc4);
    if (doA) {
        As[0][ac4 + 0][ar] = av.x; As[0][ac4 + 1][ar] = av.y;
        As[0][ac4 + 2][ar] = av.z; As[0][ac4 + 3][ar] = av.w;
    }
    if (doB) *(float4*)&Bs[0][br][bc4] = bv;
    __syncthreads();

    for (int kc = 0; kc < 16; kc++) {
        int cur = kc & 1;
        if (kc < 15) {
            if (doA) av = *(const float4*)(X + (size_t)(bm + ar) * CD + (kc + 1) * 16 + ac4);
            if (doB) bv = *(const float4*)(W + (size_t)((kc + 1) * 16 + br) * CD + bn + bc4);
        }
#pragma unroll
        for (int k = 0; k < 16; k++) {
            float2 a = *(const float2*)&As[cur][k][tr * 2];
            ull b = *(const ull*)&Bs[cur][k][tc * 2];
            acc0 = fma2(pack2(a.x, a.x), b, acc0);
            acc1 = fma2(pack2(a.y, a.y), b, acc1);
        }
        if (kc < 15) {
            int nxt = cur ^ 1;
            if (doA) {
                As[nxt][ac4 + 0][ar] = av.x; As[nxt][ac4 + 1][ar] = av.y;
                As[nxt][ac4 + 2][ar] = av.z; As[nxt][ac4 + 3][ar] = av.w;
            }
            if (doB) *(float4*)&Bs[nxt][br][bc4] = bv;
        }
        __syncthreads();
    }

    *(ull*)&G[(size_t)(bm + tr * 2 + 0) * CD + bn + tc * 2] = acc0;
    *(ull*)&G[(size_t)(bm + tr * 2 + 1) * CD + bn + tc * 2] = acc1;

    {
        float2 awv = *(const float2*)(attn_w + 2 * tc);
        float2 r0 = unpack2(acc0), r1 = unpack2(acc1);
        float s0 = awv.x * r0.x + awv.y * r0.y;
        float s1 = awv.x * r1.x + awv.y * r1.y;
#pragma unroll
        for (int off = 16; off; off >>= 1) {
            s0 += __shfl_xor_sync(0xffffffffu, s0, off);
            s1 += __shfl_xor_sync(0xffffffffu, s1, off);
        }
        if (tc == 0) {
            EC[(size_t)(bm + tr * 2 + 0) * HH + head] = 0.6f * s0;
            EC[(size_t)(bm + tr * 2 + 1) * HH + head] = 0.6f * s1;
        }
    }
}

// ---------------- fused GATv2 attention (m-split partials, f32x2) ----------------
// e[n,m,h] = ecr[n,h] + ecl[m,h] + sum_f c2[f]*|q+g|   (c2 = 0.4*aw)
// Loop structure (2 barriers/tile): e(t) -> sync -> [prefetch tile t+1 || agg(t)] -> sync
__global__ __launch_bounds__(256, 4)
void gat_kernel(const float* __restrict__ adj, const float* __restrict__ attn_w) {
    __shared__ __align__(16) float sq[BROWS][CD];        // g_r of block rows (queries)
    __shared__ __align__(16) float c2s[FF];              // 0.4*aw
    __shared__ ulonglong2 gl2[HH][FF / 4][TMm + 1];      // g_l tile, 4-f groups [h][fp2][m]
    __shared__ __align__(16) float w_t[TMm][WTS];        // [m][h*8 + n]
    __shared__ float ecr_s[BROWS * HH];                  // [n*4 + h]
    __shared__ float ecl_s[TMm * HH];                    // [m*4 + h]
    __shared__ __align__(16) float adj_s[TMm][8];        // adj tile [m][n]

    int t  = threadIdx.x;
    int n0 = blockIdx.x * BROWS;
    int sp = blockIdx.y;
    int mbase = sp * MPS;

    // load queries (as 16B) + coefficient vector + ecr
    {
        ulonglong2* sq2 = (ulonglong2*)sq;
        for (int i = t; i < BROWS * CD / 4; i += 256) {
            int r = i >> 6, c2 = i & 63;
            sq2[i] = *(const ulonglong2*)(g_gr + (size_t)(n0 + r) * CD + 4 * c2);
        }
    }
    if (t < FF) c2s[t] = 0.4f * attn_w[t];
    if (t >= 64 && t < 64 + BROWS * HH) ecr_s[t - 64] = g_ecr[n0 * HH + (t - 64)];

    // prologue: load tile 0 (gl2 + ecl + adj)
    {
        int m0 = mbase;
#pragma unroll
        for (int j = 0; j < 8; j++) {
            int i = t + j * 256;
            int m = i >> 6, cc2 = i & 63;
            gl2[cc2 >> 4][cc2 & 15][m] =
                *(const ulonglong2*)(g_gl + (size_t)(m0 + m) * CD + 4 * cc2);
        }
        if (t < TMm * HH) ecl_s[t] = g_ecl[m0 * HH + t];
        else if (t < TMm * HH + TMm * 2) {
            int i = t - TMm * HH;
            int row = i >> 1, hf = (i & 1) * 4;
            *(float4*)&adj_s[row][hf] =
                *(const float4*)(adj + (size_t)(m0 + row) * NN + n0 + hf);
        }
    }
    __syncthreads();

    int em   = t & 31;
    int wrp  = t >> 5;
    int eh   = wrp & 3;        // head
    int half = wrp >> 2;       // 0..1 -> n base = half*4
    int nb   = half * 4;

    // agg mapping: thread = output column c = t, head = c/64
    int ah = t >> 6;

    float dsum[4] = {0.f, 0.f, 0.f, 0.f};
    ull accp[4] = {0ULL, 0ULL, 0ULL, 0ULL};   // n-pairs (01,23,45,67)

    const ulonglong2* qb  = (const ulonglong2*)&sq[nb][eh * FF];  // n stride = 64 ulonglong2
    const ulonglong2* c2p = (const ulonglong2*)c2s;

    for (int tile = 0; tile < NTILES; tile++) {
        int m0 = mbase + tile * TMm;

        // ---- e-phase: e[n0+nb .. +3, m0+em, eh] ----
        {
            ull aB0 = 0, aB1 = 0, aB2 = 0, aB3 = 0;
            const ulonglong2* gp = &gl2[eh][0][em];
#pragma unroll
            for (int fp2 = 0; fp2 < FF / 4; fp2++) {
                ulonglong2 c2v = c2p[fp2];
                ulonglong2 g   = gp[fp2 * (TMm + 1)];
                ull x0, x1;
                ulonglong2 qv;
#define EABS(N, ACC) \
                qv = qb[(N) * 64 + fp2]; \
                x0 = add2(qv.x, g.x); x1 = add2(qv.y, g.y); \
                ACC = fma2(c2v.x, x0 & ABSM, ACC); \
                ACC = fma2(c2v.y, x1 & ABSM, ACC);
                EABS(0, aB0) EABS(1, aB1) EABS(2, aB2) EABS(3, aB3)
#undef EABS
            }
            float base = ecl_s[em * HH + eh];

            float4 am = *(const float4*)&adj_s[em][nb];
            float w0 = (am.x != 0.f) ? __expf(hsum2(aB0) + base + ecr_s[(nb + 0) * HH + eh]) : 0.f;
            float w1 = (am.y != 0.f) ? __expf(hsum2(aB1) + base + ecr_s[(nb + 1) * HH + eh]) : 0.f;
            float w2 = (am.z != 0.f) ? __expf(hsum2(aB2) + base + ecr_s[(nb + 2) * HH + eh]) : 0.f;
            float w3 = (am.w != 0.f) ? __expf(hsum2(aB3) + base + ecr_s[(nb + 3) * HH + eh]) : 0.f;
            dsum[0] += w0; dsum[1] += w1; dsum[2] += w2; dsum[3] += w3;
            *(float4*)&w_t[em][eh * 8 + nb] = make_float4(w0, w1, w2, w3);
        }
        __syncthreads();   // w_t ready; gl2/adj/ecl of tile t fully consumed

        // ---- overlap segment: prefetch tile t+1 into regs, run agg(t), then store ----
        bool hasNext = (tile + 1 < NTILES);
        int m1 = m0 + TMm;
        ulonglong2 gtmp[8];
        if (hasNext) {
#pragma unroll
            for (int j = 0; j < 8; j++) {
                int i = t + j * 256;
                gtmp[j] = *(const ulonglong2*)(g_gl + (size_t)(m1 + (i >> 6)) * CD + 4 * (i & 63));
            }
        }

        // aggregation: accp[np] += w[n-pair, m, ah] * (gv, gv)
        const float* grp = g_gr + (size_t)m0 * CD + t;
#pragma unroll
        for (int m = 0; m < TMm; m++) {
            float gv = __ldg(grp + (size_t)m * CD);
            ull gv2 = pack2(gv, gv);
            ulonglong2 wa = *(const ulonglong2*)&w_t[m][ah * 8];
            ulonglong2 wb = *(const ulonglong2*)&w_t[m][ah * 8 + 4];
            accp[0] = fma2(wa.x, gv2, accp[0]);
            accp[1] = fma2(wa.y, gv2, accp[1]);
            accp[2] = fma2(wb.x, gv2, accp[2]);
            accp[3] = fma2(wb.y, gv2, accp[3]);
        }

        if (hasNext) {
#pragma unroll
            for (int j = 0; j < 8; j++) {
                int i = t + j * 256;
                int cc2 = i & 63;
                gl2[cc2 >> 4][cc2 & 15][i >> 6] = gtmp[j];
            }
            if (t < TMm * HH) ecl_s[t] = g_ecl[m1 * HH + t];
            else if (t < TMm * HH + TMm * 2) {
                int i = t - TMm * HH;
                int row = i >> 1, hf = (i & 1) * 4;
                *(float4*)&adj_s[row][hf] =
                    *(const float4*)(adj + (size_t)(m1 + row) * NN + n0 + hf);
            }
        }
        __syncthreads();   // next tile staged; w_t free for e(t+1)
    }

    // reduce dsum over lanes (lanes = m slices) -> partial denominators
    {
#pragma unroll
        for (int off = 16; off; off >>= 1) {
#pragma unroll
            for (int i = 0; i < 4; i++)
                dsum[i] += __shfl_xor_sync(0xffffffffu, dsum[i], off);
        }
        if (em == 0) {
#pragma unroll
            for (int i = 0; i < 4; i++)
                g_pden[((size_t)sp * NN + n0 + nb + i) * HH + eh] = dsum[i];
        }
    }

    // partial numerators
#pragma unroll
    for (int np = 0; np < 4; np++) {
        float2 v = unpack2(accp[np]);
        g_pacc[((size_t)sp * NN + n0 + 2 * np + 0) * CD + t] = v.x;
        g_pacc[((size_t)sp * NN + n0 + 2 * np + 1) * CD + t] = v.y;
    }
}

// ---------------- combine partials + elu (float4) ----------------
__global__ __launch_bounds__(256)
void combine_kernel(const int* __restrict__ use_elu_p, float* __restrict__ out) {
    int idx = blockIdx.x * 256 + threadIdx.x;        // 0 .. 65535 (float4 slots)
    int n   = idx >> 6;
    int c4  = idx & 63;                              // float4 column
    int h   = c4 >> 4;
    float4 a = make_float4(0.f, 0.f, 0.f, 0.f);
    float  d = 0.f;
#pragma unroll
    for (int sp = 0; sp < NSPLIT; sp++) {
        float4 p = *(const float4*)&g_pacc[((size_t)sp * NN + n) * CD + 4 * c4];
        a.x += p.x; a.y += p.y; a.z += p.z; a.w += p.w;
        d += g_pden[((size_t)sp * NN + n) * HH + h];
    }
    float inv = 1.f / d;
    float4 v = make_float4(a.x * inv, a.y * inv, a.z * inv, a.w * inv);
    if (*use_elu_p) {
        v.x = (v.x > 0.f) ? v.x : expm1f(v.x);
        v.y = (v.y > 0.f) ? v.y : expm1f(v.y);
        v.z = (v.z > 0.f) ? v.z : expm1f(v.z);
        v.w = (v.w > 0.f) ? v.w : expm1f(v.w);
    }
    *(float4*)&out[(size_t)n * CD + 4 * c4] = v;
}

extern "C" void kernel_launch(void* const* d_in, const int* in_sizes, int n_in,
                              void* d_out, int out_size) {
    const float* h    = (const float*)d_in[0];
    const float* nei  = (const float*)d_in[1];
    const float* adj  = (const float*)d_in[2];
    const float* w_l  = (const float*)d_in[3];
    const float* w_r  = (const float*)d_in[4];
    const float* aw   = (const float*)d_in[5];
    const int*   uelu = (const int*)d_in[6];
    float* out = (float*)d_out;

    dim3 ggrid(CD / 64, NN / 32, 2);
    gemm_kernel<<<ggrid, 512>>>(h, w_l, nei, w_r, aw);
    dim3 agrid(NN / BROWS, NSPLIT);
    gat_kernel<<<agrid, 256>>>(adj, aw);
    combine_kernel<<<NN * CD / 4 / 256, 256>>>(uelu, out);
}

// round 11
// speedup vs baseline: 1.0314x; 1.0314x over previous
#include <cuda_runtime.h>

#define NN 1024
#define CD 256
#define HH 4
#define FF 64
#define BROWS 8
#define TMm 32
#define NSPLIT 4
#define MPS (NN / NSPLIT)      // m's per split = 256
#define NTILES (MPS / TMm)     // tiles per split = 8
#define WTS 36                 // w_t row stride (floats)

typedef unsigned long long ull;
#define ABSM 0x7FFFFFFF7FFFFFFFULL

__device__ __forceinline__ ull fma2(ull a, ull b, ull c) {
    ull d;
    asm("fma.rn.f32x2 %0, %1, %2, %3;" : "=l"(d) : "l"(a), "l"(b), "l"(c));
    return d;
}
__device__ __forceinline__ ull add2(ull a, ull b) {
    ull d;
    asm("add.rn.f32x2 %0, %1, %2;" : "=l"(d) : "l"(a), "l"(b));
    return d;
}
__device__ __forceinline__ ull pack2(float lo, float hi) {
    ull d;
    asm("mov.b64 %0, {%1, %2};" : "=l"(d) : "f"(lo), "f"(hi));
    return d;
}
__device__ __forceinline__ float2 unpack2(ull v) {
    float2 r;
    asm("mov.b64 {%0, %1}, %2;" : "=f"(r.x), "=f"(r.y) : "l"(v));
    return r;
}
__device__ __forceinline__ float hsum2(ull v) {
    float2 r = unpack2(v);
    return r.x + r.y;
}

// scratch (device globals: no allocs allowed)
__device__ float g_gl[NN * CD];
__device__ float g_gr[NN * CD];
__device__ float g_ecl[NN * HH];             // 0.6 * sum_f aw[f]*g_l[m,h,f]
__device__ float g_ecr[NN * HH];             // 0.6 * sum_f aw[f]*g_r[n,h,f]
__device__ float g_pacc[NSPLIT * NN * CD];   // partial numerators
__device__ float g_pden[NSPLIT * NN * HH];   // partial denominators

// ------- GEMM (R7 version — measured best): 32x64 tiles, 512 thr, db-buffered -------
__global__ __launch_bounds__(512)
void gemm_kernel(const float* __restrict__ X0, const float* __restrict__ W0,
                 const float* __restrict__ X1, const float* __restrict__ W1,
                 const float* __restrict__ attn_w) {
    const float* X;
    const float* W;
    float* G;
    float* EC;
    if (blockIdx.z == 0) { X = X0; W = W0; G = g_gl; EC = g_ecl; }
    else                 { X = X1; W = W1; G = g_gr; EC = g_ecr; }

    __shared__ __align__(16) float As[2][16][34];   // [buf][k][row]
    __shared__ __align__(16) float Bs[2][16][64];   // [buf][k][col]

    int t = threadIdx.x;
    int bm = blockIdx.y * 32;
    int bn = blockIdx.x * 64;
    int head = blockIdx.x;     // bn = head*64
    int tr = t >> 5;           // warp id 0..15 -> rows 2tr, 2tr+1
    int tc = t & 31;           // lane -> cols 2tc, 2tc+1

    int ar  = t >> 2;            // 0..31 (t<128)
    int ac4 = (t & 3) << 2;
    int bi  = t - 128;           // valid for t in [128,384)
    int br  = bi >> 4;
    int bc4 = (bi & 15) << 2;
    bool doA = (t < 128);
    bool doB = (t >= 128 && t < 384);

    ull acc0 = 0, acc1 = 0;

    float4 av, bv;
    if (doA) av = *(const float4*)(X + (size_t)(bm + ar) * CD + ac4);
    if (doB) bv = *(const float4*)(W + (size_t)br * CD + bn + bc4);
    if (doA) {
        As[0][ac4 + 0][ar] = av.x; As[0][ac4 + 1][ar] = av.y;
        As[0][ac4 + 2][ar] = av.z; As[0][ac4 + 3][ar] = av.w;
    }
    if (doB) *(float4*)&Bs[0][br][bc4] = bv;
    __syncthreads();

    for (int kc = 0; kc < 16; kc++) {
        int cur = kc & 1;
        if (kc < 15) {
            if (doA) av = *(const float4*)(X + (size_t)(bm + ar) * CD + (kc + 1) * 16 + ac4);
            if (doB) bv = *(const float4*)(W + (size_t)((kc + 1) * 16 + br) * CD + bn + bc4);
        }
#pragma unroll
        for (int k = 0; k < 16; k++) {
            float2 a = *(const float2*)&As[cur][k][tr * 2];
            ull b = *(const ull*)&Bs[cur][k][tc * 2];
            acc0 = fma2(pack2(a.x, a.x), b, acc0);
            acc1 = fma2(pack2(a.y, a.y), b, acc1);
        }
        if (kc < 15) {
            int nxt = cur ^ 1;
            if (doA) {
                As[nxt][ac4 + 0][ar] = av.x; As[nxt][ac4 + 1][ar] = av.y;
                As[nxt][ac4 + 2][ar] = av.z; As[nxt][ac4 + 3][ar] = av.w;
            }
            if (doB) *(float4*)&Bs[nxt][br][bc4] = bv;
        }
        __syncthreads();
    }

    *(ull*)&G[(size_t)(bm + tr * 2 + 0) * CD + bn + tc * 2] = acc0;
    *(ull*)&G[(size_t)(bm + tr * 2 + 1) * CD + bn + tc * 2] = acc1;

    {
        float2 awv = *(const float2*)(attn_w + 2 * tc);
        float2 r0 = unpack2(acc0), r1 = unpack2(acc1);
        float s0 = awv.x * r0.x + awv.y * r0.y;
        float s1 = awv.x * r1.x + awv.y * r1.y;
#pragma unroll
        for (int off = 16; off; off >>= 1) {
            s0 += __shfl_xor_sync(0xffffffffu, s0, off);
            s1 += __shfl_xor_sync(0xffffffffu, s1, off);
        }
        if (tc == 0) {
            EC[(size_t)(bm + tr * 2 + 0) * HH + head] = 0.6f * s0;
            EC[(size_t)(bm + tr * 2 + 1) * HH + head] = 0.6f * s1;
        }
    }
}

// ---------------- fused GATv2 attention (m-split partials, f32x2) ----------------
// e[n,m,h] = ecr[n,h] + ecl[m,h] + sum_f c2[f]*|q+g|   (c2 = 0.4*aw)
// 2 barriers/tile; tile(t+1) staged in two 16-reg segments interleaved with agg(t).
__global__ __launch_bounds__(256, 4)
void gat_kernel(const float* __restrict__ adj, const float* __restrict__ attn_w) {
    __shared__ __align__(16) float sq[BROWS][CD];        // g_r of block rows (queries)
    __shared__ __align__(16) float c2s[FF];              // 0.4*aw
    __shared__ ulonglong2 gl2[HH][FF / 4][TMm + 1];      // g_l tile, 4-f groups [h][fp2][m]
    __shared__ __align__(16) float w_t[TMm][WTS];        // [m][h*8 + n]
    __shared__ float ecr_s[BROWS * HH];                  // [n*4 + h]
    __shared__ float ecl_s[TMm * HH];                    // [m*4 + h]
    __shared__ __align__(16) float adj_s[TMm][8];        // adj tile [m][n]

    int t  = threadIdx.x;
    int n0 = blockIdx.x * BROWS;
    int sp = blockIdx.y;
    int mbase = sp * MPS;

    // load queries (as 16B) + coefficient vector + ecr
    {
        ulonglong2* sq2 = (ulonglong2*)sq;
        for (int i = t; i < BROWS * CD / 4; i += 256) {
            int r = i >> 6, c2 = i & 63;
            sq2[i] = *(const ulonglong2*)(g_gr + (size_t)(n0 + r) * CD + 4 * c2);
        }
    }
    if (t < FF) c2s[t] = 0.4f * attn_w[t];
    if (t >= 64 && t < 64 + BROWS * HH) ecr_s[t - 64] = g_ecr[n0 * HH + (t - 64)];

    // prologue: load tile 0 (gl2 + ecl + adj)
    {
        int m0 = mbase;
#pragma unroll
        for (int j = 0; j < 8; j++) {
            int i = t + j * 256;
            int m = i >> 6, cc2 = i & 63;
            gl2[cc2 >> 4][cc2 & 15][m] =
                *(const ulonglong2*)(g_gl + (size_t)(m0 + m) * CD + 4 * cc2);
        }
        if (t < TMm * HH) ecl_s[t] = g_ecl[m0 * HH + t];
        else if (t < TMm * HH + TMm * 2) {
            int i = t - TMm * HH;
            int row = i >> 1, hf = (i & 1) * 4;
            *(float4*)&adj_s[row][hf] =
                *(const float4*)(adj + (size_t)(m0 + row) * NN + n0 + hf);
        }
    }
    __syncthreads();

    int em   = t & 31;
    int wrp  = t >> 5;
    int eh   = wrp & 3;        // head
    int half = wrp >> 2;       // 0..1 -> n base = half*4
    int nb   = half * 4;

    // agg mapping: thread = output column c = t, head = c/64
    int ah = t >> 6;

    float dsum[4] = {0.f, 0.f, 0.f, 0.f};
    ull accp[4] = {0ULL, 0ULL, 0ULL, 0ULL};   // n-pairs (01,23,45,67)

    const ulonglong2* qb  = (const ulonglong2*)&sq[nb][eh * FF];  // n stride = 64 ulonglong2
    const ulonglong2* c2p = (const ulonglong2*)c2s;

    for (int tile = 0; tile < NTILES; tile++) {
        int m0 = mbase + tile * TMm;

        // ---- e-phase: e[n0+nb .. +3, m0+em, eh] ----
        {
            ull aB0 = 0, aB1 = 0, aB2 = 0, aB3 = 0;
            const ulonglong2* gp = &gl2[eh][0][em];
#pragma unroll
            for (int fp2 = 0; fp2 < FF / 4; fp2++) {
                ulonglong2 c2v = c2p[fp2];
                ulonglong2 g   = gp[fp2 * (TMm + 1)];
                ull x0, x1;
                ulonglong2 qv;
#define EABS(N, ACC) \
                qv = qb[(N) * 64 + fp2]; \
                x0 = add2(qv.x, g.x); x1 = add2(qv.y, g.y); \
                ACC = fma2(c2v.x, x0 & ABSM, ACC); \
                ACC = fma2(c2v.y, x1 & ABSM, ACC);
                EABS(0, aB0) EABS(1, aB1) EABS(2, aB2) EABS(3, aB3)
#undef EABS
            }
            float base = ecl_s[em * HH + eh];

            float4 am = *(const float4*)&adj_s[em][nb];
            float w0 = (am.x != 0.f) ? __expf(hsum2(aB0) + base + ecr_s[(nb + 0) * HH + eh]) : 0.f;
            float w1 = (am.y != 0.f) ? __expf(hsum2(aB1) + base + ecr_s[(nb + 1) * HH + eh]) : 0.f;
            float w2 = (am.z != 0.f) ? __expf(hsum2(aB2) + base + ecr_s[(nb + 2) * HH + eh]) : 0.f;
            float w3 = (am.w != 0.f) ? __expf(hsum2(aB3) + base + ecr_s[(nb + 3) * HH + eh]) : 0.f;
            dsum[0] += w0; dsum[1] += w1; dsum[2] += w2; dsum[3] += w3;
            *(float4*)&w_t[em][eh * 8 + nb] = make_float4(w0, w1, w2, w3);
        }
        __syncthreads();   // e(t) done in all warps: gl2/adj/ecl free, w_t ready

        bool hasNext = (tile + 1 < NTILES);
        int m1 = m0 + TMm;
        const float* grp = g_gr + (size_t)m0 * CD + t;

        // ---- segment 1: prefetch first half of gl2(t+1), agg m 0..15, store ----
        {
            ulonglong2 gtmp[4];    // 16 regs
            if (hasNext) {
#pragma unroll
                for (int j = 0; j < 4; j++) {
                    int i = t + j * 256;                  // m 0..15
                    gtmp[j] = *(const ulonglong2*)(g_gl + (size_t)(m1 + (i >> 6)) * CD + 4 * (i & 63));
                }
            }
#pragma unroll
            for (int m = 0; m < 16; m++) {
                float gv = __ldg(grp + (size_t)m * CD);
                ull gv2 = pack2(gv, gv);
                ulonglong2 wa = *(const ulonglong2*)&w_t[m][ah * 8];
                ulonglong2 wb = *(const ulonglong2*)&w_t[m][ah * 8 + 4];
                accp[0] = fma2(wa.x, gv2, accp[0]);
                accp[1] = fma2(wa.y, gv2, accp[1]);
                accp[2] = fma2(wb.x, gv2, accp[2]);
                accp[3] = fma2(wb.y, gv2, accp[3]);
            }
            if (hasNext) {
#pragma unroll
                for (int j = 0; j < 4; j++) {
                    int i = t + j * 256;
                    int cc2 = i & 63;
                    gl2[cc2 >> 4][cc2 & 15][i >> 6] = gtmp[j];
                }
            }
        }
        // ---- segment 2: prefetch second half, agg m 16..31, store ----
        {
            ulonglong2 gtmp[4];
            if (hasNext) {
#pragma unroll
                for (int j = 4; j < 8; j++) {
                    int i = t + j * 256;                  // m 16..31
                    gtmp[j - 4] = *(const ulonglong2*)(g_gl + (size_t)(m1 + (i >> 6)) * CD + 4 * (i & 63));
                }
            }
#pragma unroll
            for (int m = 16; m < 32; m++) {
                float gv = __ldg(grp + (size_t)m * CD);
                ull gv2 = pack2(gv, gv);
                ulonglong2 wa = *(const ulonglong2*)&w_t[m][ah * 8];
                ulonglong2 wb = *(const ulonglong2*)&w_t[m][ah * 8 + 4];
                accp[0] = fma2(wa.x, gv2, accp[0]);
                accp[1] = fma2(wa.y, gv2, accp[1]);
                accp[2] = fma2(wb.x, gv2, accp[2]);
                accp[3] = fma2(wb.y, gv2, accp[3]);
            }
            if (hasNext) {
#pragma unroll
                for (int j = 4; j < 8; j++) {
                    int i = t + j * 256;
                    int cc2 = i & 63;
                    gl2[cc2 >> 4][cc2 & 15][i >> 6] = gtmp[j - 4];
                }
            }
        }
        // ---- ecl/adj for t+1 ----
        if (hasNext) {
            if (t < TMm * HH) ecl_s[t] = g_ecl[m1 * HH + t];
            else if (t < TMm * HH + TMm * 2) {
                int i = t - TMm * HH;
                int row = i >> 1, hf = (i & 1) * 4;
                *(float4*)&adj_s[row][hf] =
                    *(const float4*)(adj + (size_t)(m1 + row) * NN + n0 + hf);
            }
        }
        __syncthreads();   // tile t+1 staged; agg(t) done -> w_t free for e(t+1)
    }

    // reduce dsum over lanes (lanes = m slices) -> partial denominators
    {
#pragma unroll
        for (int off = 16; off; off >>= 1) {
#pragma unroll
            for (int i = 0; i < 4; i++)
                dsum[i] += __shfl_xor_sync(0xffffffffu, dsum[i], off);
        }
        if (em == 0) {
#pragma unroll
            for (int i = 0; i < 4; i++)
                g_pden[((size_t)sp * NN + n0 + nb + i) * HH + eh] = dsum[i];
        }
    }

    // partial numerators
#pragma unroll
    for (int np = 0; np < 4; np++) {
        float2 v = unpack2(accp[np]);
        g_pacc[((size_t)sp * NN + n0 + 2 * np + 0) * CD + t] = v.x;
        g_pacc[((size_t)sp * NN + n0 + 2 * np + 1) * CD + t] = v.y;
    }
}

// ---------------- combine partials + elu (float4) ----------------
__global__ __launch_bounds__(256)
void combine_kernel(const int* __restrict__ use_elu_p, float* __restrict__ out) {
    int idx = blockIdx.x * 256 + threadIdx.x;        // 0 .. 65535 (float4 slots)
    int n   = idx >> 6;
    int c4  = idx & 63;                              // float4 column
    int h   = c4 >> 4;
    float4 a = make_float4(0.f, 0.f, 0.f, 0.f);
    float  d = 0.f;
#pragma unroll
    for (int sp = 0; sp < NSPLIT; sp++) {
        float4 p = *(const float4*)&g_pacc[((size_t)sp * NN + n) * CD + 4 * c4];
        a.x += p.x; a.y += p.y; a.z += p.z; a.w += p.w;
        d += g_pden[((size_t)sp * NN + n) * HH + h];
    }
    float inv = 1.f / d;
    float4 v = make_float4(a.x * inv, a.y * inv, a.z * inv, a.w * inv);
    if (*use_elu_p) {
        v.x = (v.x > 0.f) ? v.x : expm1f(v.x);
        v.y = (v.y > 0.f) ? v.y : expm1f(v.y);
        v.z = (v.z > 0.f) ? v.z : expm1f(v.z);
        v.w = (v.w > 0.f) ? v.w : expm1f(v.w);
    }
    *(float4*)&out[(size_t)n * CD + 4 * c4] = v;
}

extern "C" void kernel_launch(void* const* d_in, const int* in_sizes, int n_in,
                              void* d_out, int out_size) {
    const float* h    = (const float*)d_in[0];
    const float* nei  = (const float*)d_in[1];
    const float* adj  = (const float*)d_in[2];
    const float* w_l  = (const float*)d_in[3];
    const float* w_r  = (const float*)d_in[4];
    const float* aw   = (const float*)d_in[5];
    const int*   uelu = (const int*)d_in[6];
    float* out = (float*)d_out;

    dim3 ggrid(CD / 64, NN / 32, 2);
    gemm_kernel<<<ggrid, 512>>>(h, w_l, nei, w_r, aw);
    dim3 agrid(NN / BROWS, NSPLIT);
    gat_kernel<<<agrid, 256>>>(adj, aw);
    combine_kernel<<<NN * CD / 4 / 256, 256>>>(uelu, out);
}

// round 12
// speedup vs baseline: 1.1507x; 1.1156x over previous
#include <cuda_runtime.h>

#define NN 1024
#define CD 256
#define HH 4
#define FF 64
#define BROWS 16
#define TMm 32
#define NSPLIT 4
#define MPS (NN / NSPLIT)      // m's per split = 256
#define NTILES (MPS / TMm)     // tiles per split = 8
#define WTS 68                 // w_t row stride (floats): [m][h*16 + n], pad 4
#define ADJS 20                // adj_s row stride (floats), conflict-free LDS.128

typedef unsigned long long ull;
#define ABSM 0x7FFFFFFF7FFFFFFFULL

__device__ __forceinline__ ull fma2(ull a, ull b, ull c) {
    ull d;
    asm("fma.rn.f32x2 %0, %1, %2, %3;" : "=l"(d) : "l"(a), "l"(b), "l"(c));
    return d;
}
__device__ __forceinline__ ull add2(ull a, ull b) {
    ull d;
    asm("add.rn.f32x2 %0, %1, %2;" : "=l"(d) : "l"(a), "l"(b));
    return d;
}
__device__ __forceinline__ ull pack2(float lo, float hi) {
    ull d;
    asm("mov.b64 %0, {%1, %2};" : "=l"(d) : "f"(lo), "f"(hi));
    return d;
}
__device__ __forceinline__ float2 unpack2(ull v) {
    float2 r;
    asm("mov.b64 {%0, %1}, %2;" : "=f"(r.x), "=f"(r.y) : "l"(v));
    return r;
}
__device__ __forceinline__ float hsum2(ull v) {
    float2 r = unpack2(v);
    return r.x + r.y;
}

// scratch (device globals: no allocs allowed)
__device__ float g_gl[NN * CD];
__device__ float g_gr[NN * CD];
__device__ float g_ecl[NN * HH];             // 0.6 * sum_f aw[f]*g_l[m,h,f]
__device__ float g_ecr[NN * HH];             // 0.6 * sum_f aw[f]*g_r[n,h,f]
__device__ float g_pacc[NSPLIT * NN * CD];   // partial numerators
__device__ float g_pden[NSPLIT * NN * HH];   // partial denominators

// ------- GEMM (R7 version — measured best): 32x64 tiles, 512 thr, db-buffered -------
__global__ __launch_bounds__(512)
void gemm_kernel(const float* __restrict__ X0, const float* __restrict__ W0,
                 const float* __restrict__ X1, const float* __restrict__ W1,
                 const float* __restrict__ attn_w) {
    const float* X;
    const float* W;
    float* G;
    float* EC;
    if (blockIdx.z == 0) { X = X0; W = W0; G = g_gl; EC = g_ecl; }
    else                 { X = X1; W = W1; G = g_gr; EC = g_ecr; }

    __shared__ __align__(16) float As[2][16][34];   // [buf][k][row]
    __shared__ __align__(16) float Bs[2][16][64];   // [buf][k][col]

    int t = threadIdx.x;
    int bm = blockIdx.y * 32;
    int bn = blockIdx.x * 64;
    int head = blockIdx.x;     // bn = head*64
    int tr = t >> 5;           // warp id 0..15 -> rows 2tr, 2tr+1
    int tc = t & 31;           // lane -> cols 2tc, 2tc+1

    int ar  = t >> 2;            // 0..31 (t<128)
    int ac4 = (t & 3) << 2;
    int bi  = t - 128;           // valid for t in [128,384)
    int br  = bi >> 4;
    int bc4 = (bi & 15) << 2;
    bool doA = (t < 128);
    bool doB = (t >= 128 && t < 384);

    ull acc0 = 0, acc1 = 0;

    float4 av, bv;
    if (doA) av = *(const float4*)(X + (size_t)(bm + ar) * CD + ac4);
    if (doB) bv = *(const float4*)(W + (size_t)br * CD + bn + bc4);
    if (doA) {
        As[0][ac4 + 0][ar] = av.x; As[0][ac4 + 1][ar] = av.y;
        As[0][ac4 + 2][ar] = av.z; As[0][ac4 + 3][ar] = av.w;
    }
    if (doB) *(float4*)&Bs[0][br][bc4] = bv;
    __syncthreads();

    for (int kc = 0; kc < 16; kc++) {
        int cur = kc & 1;
        if (kc < 15) {
            if (doA) av = *(const float4*)(X + (size_t)(bm + ar) * CD + (kc + 1) * 16 + ac4);
            if (doB) bv = *(const float4*)(W + (size_t)((kc + 1) * 16 + br) * CD + bn + bc4);
        }
#pragma unroll
        for (int k = 0; k < 16; k++) {
            float2 a = *(const float2*)&As[cur][k][tr * 2];
            ull b = *(const ull*)&Bs[cur][k][tc * 2];
            acc0 = fma2(pack2(a.x, a.x), b, acc0);
            acc1 = fma2(pack2(a.y, a.y), b, acc1);
        }
        if (kc < 15) {
            int nxt = cur ^ 1;
            if (doA) {
                As[nxt][ac4 + 0][ar] = av.x; As[nxt][ac4 + 1][ar] = av.y;
                As[nxt][ac4 + 2][ar] = av.z; As[nxt][ac4 + 3][ar] = av.w;
            }
            if (doB) *(float4*)&Bs[nxt][br][bc4] = bv;
        }
        __syncthreads();
    }

    *(ull*)&G[(size_t)(bm + tr * 2 + 0) * CD + bn + tc * 2] = acc0;
    *(ull*)&G[(size_t)(bm + tr * 2 + 1) * CD + bn + tc * 2] = acc1;

    {
        float2 awv = *(const float2*)(attn_w + 2 * tc);
        float2 r0 = unpack2(acc0), r1 = unpack2(acc1);
        float s0 = awv.x * r0.x + awv.y * r0.y;
        float s1 = awv.x * r1.x + awv.y * r1.y;
#pragma unroll
        for (int off = 16; off; off >>= 1) {
            s0 += __shfl_xor_sync(0xffffffffu, s0, off);
            s1 += __shfl_xor_sync(0xffffffffu, s1, off);
        }
        if (tc == 0) {
            EC[(size_t)(bm + tr * 2 + 0) * HH + head] = 0.6f * s0;
            EC[(size_t)(bm + tr * 2 + 1) * HH + head] = 0.6f * s1;
        }
    }
}

// ---------------- fused GATv2 attention (m-split partials, f32x2) ----------------
// e[n,m,h] = ecr[n,h] + ecl[m,h] + sum_f c2[f]*|q+g|   (c2 = 0.4*aw)
// BROWS=16, 512 threads. e-phase: 16 warps, warp=(eh, quarter), 4 n each.
// agg: c = t&255, n-half = t>>8 (8 n each, 4 accp pairs).
__global__ __launch_bounds__(512, 2)
void gat_kernel(const float* __restrict__ adj, const float* __restrict__ attn_w) {
    __shared__ __align__(16) float sq[BROWS][CD];        // g_r of block rows (queries)
    __shared__ __align__(16) float c2s[FF];              // 0.4*aw
    __shared__ ulonglong2 gl2[HH][FF / 4][TMm + 1];      // g_l tile, 4-f groups [h][fp2][m]
    __shared__ __align__(16) float w_t[TMm][WTS];        // [m][h*16 + n]
    __shared__ float ecr_s[BROWS * HH];                  // [n*4 + h]
    __shared__ float ecl_s[TMm * HH];                    // [m*4 + h]
    __shared__ __align__(16) float adj_s[TMm][ADJS];     // adj tile [m][n]

    int t  = threadIdx.x;
    int n0 = blockIdx.x * BROWS;
    int sp = blockIdx.y;
    int mbase = sp * MPS;

    // load queries (as 16B) + coefficient vector + ecr
    {
        ulonglong2* sq2 = (ulonglong2*)sq;
        for (int i = t; i < BROWS * CD / 4; i += 512) {
            int r = i >> 6, c2 = i & 63;
            sq2[i] = *(const ulonglong2*)(g_gr + (size_t)(n0 + r) * CD + 4 * c2);
        }
    }
    if (t < FF) c2s[t] = 0.4f * attn_w[t];
    if (t >= 64 && t < 64 + BROWS * HH) ecr_s[t - 64] = g_ecr[n0 * HH + (t - 64)];

    int em   = t & 31;
    int wrp  = t >> 5;         // 0..15
    int eh   = wrp & 3;        // head
    int nb   = (wrp >> 2) * 4; // n base within block: 0,4,8,12

    // agg mapping
    int ac  = t & 255;         // output column
    int ah  = ac >> 6;         // head for w_t reads
    int nb8 = (t >> 8) * 8;    // n base (0 or 8)

    float dsum[4] = {0.f, 0.f, 0.f, 0.f};
    ull accp[4] = {0ULL, 0ULL, 0ULL, 0ULL};   // n-pairs within my 8-n group

    const ulonglong2* qb  = (const ulonglong2*)&sq[nb][eh * FF];  // n stride = 64 ulonglong2
    const ulonglong2* c2p = (const ulonglong2*)c2s;

    for (int tile = 0; tile < NTILES; tile++) {
        int m0 = mbase + tile * TMm;
        __syncthreads();  // previous agg done before overwriting gl2 / w_t

        // load g_l tile as 16B groups: gl2[h][fp2][m]; plus ecl + adj tiles
#pragma unroll
        for (int j = 0; j < 4; j++) {
            int i = t + j * 512;
            int m = i >> 6, cc2 = i & 63;
            gl2[cc2 >> 4][cc2 & 15][m] =
                *(const ulonglong2*)(g_gl + (size_t)(m0 + m) * CD + 4 * cc2);
        }
        if (t < TMm * HH) ecl_s[t] = g_ecl[m0 * HH + t];
        else if (t < TMm * HH + TMm * 4) {
            int i = t - TMm * HH;      // 0..127
            int row = i >> 2, hf = (i & 3) * 4;
            *(float4*)&adj_s[row][hf] =
                *(const float4*)(adj + (size_t)(m0 + row) * NN + n0 + hf);
        }
        __syncthreads();

        // ---- e-phase: e[n0+nb .. +3, m0+em, eh] ----
        {
            ull aB0 = 0, aB1 = 0, aB2 = 0, aB3 = 0;
            const ulonglong2* gp = &gl2[eh][0][em];
#pragma unroll
            for (int fp2 = 0; fp2 < FF / 4; fp2++) {
                ulonglong2 c2v = c2p[fp2];
                ulonglong2 g   = gp[fp2 * (TMm + 1)];
                ull x0, x1;
                ulonglong2 qv;
#define EABS(N, ACC) \
                qv = qb[(N) * 64 + fp2]; \
                x0 = add2(qv.x, g.x); x1 = add2(qv.y, g.y); \
                ACC = fma2(c2v.x, x0 & ABSM, ACC); \
                ACC = fma2(c2v.y, x1 & ABSM, ACC);
                EABS(0, aB0) EABS(1, aB1) EABS(2, aB2) EABS(3, aB3)
#undef EABS
            }
            float base = ecl_s[em * HH + eh];

            float4 am = *(const float4*)&adj_s[em][nb];
            float w0 = (am.x != 0.f) ? __expf(hsum2(aB0) + base + ecr_s[(nb + 0) * HH + eh]) : 0.f;
            float w1 = (am.y != 0.f) ? __expf(hsum2(aB1) + base + ecr_s[(nb + 1) * HH + eh]) : 0.f;
            float w2 = (am.z != 0.f) ? __expf(hsum2(aB2) + base + ecr_s[(nb + 2) * HH + eh]) : 0.f;
            float w3 = (am.w != 0.f) ? __expf(hsum2(aB3) + base + ecr_s[(nb + 3) * HH + eh]) : 0.f;
            dsum[0] += w0; dsum[1] += w1; dsum[2] += w2; dsum[3] += w3;
            *(float4*)&w_t[em][eh * 16 + nb] = make_float4(w0, w1, w2, w3);
        }
        __syncthreads();

        // ---- aggregation: software-pipelined g prefetch (MLP=8) ----
        const float* grp = g_gr + (size_t)m0 * CD + ac;
        float gpref[8];
#pragma unroll
        for (int j = 0; j < 8; j++) gpref[j] = __ldg(grp + (size_t)j * CD);
#pragma unroll
        for (int ch = 0; ch < 4; ch++) {
            float gcur[8];
#pragma unroll
            for (int j = 0; j < 8; j++) gcur[j] = gpref[j];
            if (ch < 3) {
#pragma unroll
                for (int j = 0; j < 8; j++)
                    gpref[j] = __ldg(grp + (size_t)((ch + 1) * 8 + j) * CD);
            }
#pragma unroll
            for (int j = 0; j < 8; j++) {
                int m = ch * 8 + j;
                ull gv2 = pack2(gcur[j], gcur[j]);
                ulonglong2 wa = *(const ulonglong2*)&w_t[m][ah * 16 + nb8];
                ulonglong2 wb = *(const ulonglong2*)&w_t[m][ah * 16 + nb8 + 4];
                accp[0] = fma2(wa.x, gv2, accp[0]);
                accp[1] = fma2(wa.y, gv2, accp[1]);
                accp[2] = fma2(wb.x, gv2, accp[2]);
                accp[3] = fma2(wb.y, gv2, accp[3]);
            }
        }
    }

    // reduce dsum over lanes (lanes = m slices) -> partial denominators
    {
#pragma unroll
        for (int off = 16; off; off >>= 1) {
#pragma unroll
            for (int i = 0; i < 4; i++)
                dsum[i] += __shfl_xor_sync(0xffffffffu, dsum[i], off);
        }
        if (em == 0) {
#pragma unroll
            for (int i = 0; i < 4; i++)
                g_pden[((size_t)sp * NN + n0 + nb + i) * HH + eh] = dsum[i];
        }
    }

    // partial numerators (8 n's per thread, column ac)
#pragma unroll
    for (int np = 0; np < 4; np++) {
        float2 v = unpack2(accp[np]);
        g_pacc[((size_t)sp * NN + n0 + nb8 + 2 * np + 0) * CD + ac] = v.x;
        g_pacc[((size_t)sp * NN + n0 + nb8 + 2 * np + 1) * CD + ac] = v.y;
    }
}

// ---------------- combine partials + elu (float4) ----------------
__global__ __launch_bounds__(256)
void combine_kernel(const int* __restrict__ use_elu_p, float* __restrict__ out) {
    int idx = blockIdx.x * 256 + threadIdx.x;        // 0 .. 65535 (float4 slots)
    int n   = idx >> 6;
    int c4  = idx & 63;                              // float4 column
    int h   = c4 >> 4;
    float4 a = make_float4(0.f, 0.f, 0.f, 0.f);
    float  d = 0.f;
#pragma unroll
    for (int sp = 0; sp < NSPLIT; sp++) {
        float4 p = *(const float4*)&g_pacc[((size_t)sp * NN + n) * CD + 4 * c4];
        a.x += p.x; a.y += p.y; a.z += p.z; a.w += p.w;
        d += g_pden[((size_t)sp * NN + n) * HH + h];
    }
    float inv = 1.f / d;
    float4 v = make_float4(a.x * inv, a.y * inv, a.z * inv, a.w * inv);
    if (*use_elu_p) {
        v.x = (v.x > 0.f) ? v.x : expm1f(v.x);
        v.y = (v.y > 0.f) ? v.y : expm1f(v.y);
        v.z = (v.z > 0.f) ? v.z : expm1f(v.z);
        v.w = (v.w > 0.f) ? v.w : expm1f(v.w);
    }
    *(float4*)&out[(size_t)n * CD + 4 * c4] = v;
}

extern "C" void kernel_launch(void* const* d_in, const int* in_sizes, int n_in,
                              void* d_out, int out_size) {
    const float* h    = (const float*)d_in[0];
    const float* nei  = (const float*)d_in[1];
    const float* adj  = (const float*)d_in[2];
    const float* w_l  = (const float*)d_in[3];
    const float* w_r  = (const float*)d_in[4];
    const float* aw   = (const float*)d_in[5];
    const int*   uelu = (const int*)d_in[6];
    float* out = (float*)d_out;

    dim3 ggrid(CD / 64, NN / 32, 2);
    gemm_kernel<<<ggrid, 512>>>(h, w_l, nei, w_r, aw);
    dim3 agrid(NN / BROWS, NSPLIT);
    gat_kernel<<<agrid, 512>>>(adj, aw);
    combine_kernel<<<NN * CD / 4 / 256, 256>>>(uelu, out);
}

// round 13
// speedup vs baseline: 1.1654x; 1.0128x over previous
#include <cuda_runtime.h>

#define NN 1024
#define CD 256
#define HH 4
#define FF 64
#define BROWS 32
#define TMm 32
#define NSPLIT 4
#define MPS (NN / NSPLIT)      // m's per split = 256
#define NTILES (MPS / TMm)     // tiles per split = 8
#define WTS 132                // w_t row stride (floats): [m][h*32 + n], pad 4
#define ADJS 36                // adj_s row stride (floats)

typedef unsigned long long ull;
#define ABSM 0x7FFFFFFF7FFFFFFFULL

__device__ __forceinline__ ull fma2(ull a, ull b, ull c) {
    ull d;
    asm("fma.rn.f32x2 %0, %1, %2, %3;" : "=l"(d) : "l"(a), "l"(b), "l"(c));
    return d;
}
__device__ __forceinline__ ull add2(ull a, ull b) {
    ull d;
    asm("add.rn.f32x2 %0, %1, %2;" : "=l"(d) : "l"(a), "l"(b));
    return d;
}
__device__ __forceinline__ ull pack2(float lo, float hi) {
    ull d;
    asm("mov.b64 %0, {%1, %2};" : "=l"(d) : "f"(lo), "f"(hi));
    return d;
}
__device__ __forceinline__ float2 unpack2(ull v) {
    float2 r;
    asm("mov.b64 {%0, %1}, %2;" : "=f"(r.x), "=f"(r.y) : "l"(v));
    return r;
}
__device__ __forceinline__ float hsum2(ull v) {
    float2 r = unpack2(v);
    return r.x + r.y;
}

// scratch (device globals: no allocs allowed)
__device__ float g_gl[NN * CD];
__device__ float g_gr[NN * CD];
__device__ float g_ecl[NN * HH];             // 0.6 * sum_f aw[f]*g_l[m,h,f]
__device__ float g_ecr[NN * HH];             // 0.6 * sum_f aw[f]*g_r[n,h,f]
__device__ float g_pacc[NSPLIT * NN * CD];   // partial numerators
__device__ float g_pden[NSPLIT * NN * HH];   // partial denominators

// gat dynamic-smem layout
struct GatSmem {
    float sq[BROWS][CD];                     // 32768 B  (16-aligned base)
    ulonglong2 gl2[HH][FF / 4][TMm + 1];     // 33792 B
    float w_t[TMm][WTS];                     // 16896 B
    float adj_s[TMm][ADJS];                  //  4608 B
    float c2s[FF];
    float ecr_s[BROWS * HH];
    float ecl_s[TMm * HH];
};                                           // ~89.3 KB

// ------- GEMM (R7 version — measured best): 32x64 tiles, 512 thr, db-buffered -------
__global__ __launch_bounds__(512)
void gemm_kernel(const float* __restrict__ X0, const float* __restrict__ W0,
                 const float* __restrict__ X1, const float* __restrict__ W1,
                 const float* __restrict__ attn_w) {
    const float* X;
    const float* W;
    float* G;
    float* EC;
    if (blockIdx.z == 0) { X = X0; W = W0; G = g_gl; EC = g_ecl; }
    else                 { X = X1; W = W1; G = g_gr; EC = g_ecr; }

    __shared__ __align__(16) float As[2][16][34];   // [buf][k][row]
    __shared__ __align__(16) float Bs[2][16][64];   // [buf][k][col]

    int t = threadIdx.x;
    int bm = blockIdx.y * 32;
    int bn = blockIdx.x * 64;
    int head = blockIdx.x;     // bn = head*64
    int tr = t >> 5;           // warp id 0..15 -> rows 2tr, 2tr+1
    int tc = t & 31;           // lane -> cols 2tc, 2tc+1

    int ar  = t >> 2;            // 0..31 (t<128)
    int ac4 = (t & 3) << 2;
    int bi  = t - 128;           // valid for t in [128,384)
    int br  = bi >> 4;
    int bc4 = (bi & 15) << 2;
    bool doA = (t < 128);
    bool doB = (t >= 128 && t < 384);

    ull acc0 = 0, acc1 = 0;

    float4 av, bv;
    if (doA) av = *(const float4*)(X + (size_t)(bm + ar) * CD + ac4);
    if (doB) bv = *(const float4*)(W + (size_t)br * CD + bn + bc4);
    if (doA) {
        As[0][ac4 + 0][ar] = av.x; As[0][ac4 + 1][ar] = av.y;
        As[0][ac4 + 2][ar] = av.z; As[0][ac4 + 3][ar] = av.w;
    }
    if (doB) *(float4*)&Bs[0][br][bc4] = bv;
    __syncthreads();

    for (int kc = 0; kc < 16; kc++) {
        int cur = kc & 1;
        if (kc < 15) {
            if (doA) av = *(const float4*)(X + (size_t)(bm + ar) * CD + (kc + 1) * 16 + ac4);
            if (doB) bv = *(const float4*)(W + (size_t)((kc + 1) * 16 + br) * CD + bn + bc4);
        }
#pragma unroll
        for (int k = 0; k < 16; k++) {
            float2 a = *(const float2*)&As[cur][k][tr * 2];
            ull b = *(const ull*)&Bs[cur][k][tc * 2];
            acc0 = fma2(pack2(a.x, a.x), b, acc0);
            acc1 = fma2(pack2(a.y, a.y), b, acc1);
        }
        if (kc < 15) {
            int nxt = cur ^ 1;
            if (doA) {
                As[nxt][ac4 + 0][ar] = av.x; As[nxt][ac4 + 1][ar] = av.y;
                As[nxt][ac4 + 2][ar] = av.z; As[nxt][ac4 + 3][ar] = av.w;
            }
            if (doB) *(float4*)&Bs[nxt][br][bc4] = bv;
        }
        __syncthreads();
    }

    *(ull*)&G[(size_t)(bm + tr * 2 + 0) * CD + bn + tc * 2] = acc0;
    *(ull*)&G[(size_t)(bm + tr * 2 + 1) * CD + bn + tc * 2] = acc1;

    {
        float2 awv = *(const float2*)(attn_w + 2 * tc);
        float2 r0 = unpack2(acc0), r1 = unpack2(acc1);
        float s0 = awv.x * r0.x + awv.y * r0.y;
        float s1 = awv.x * r1.x + awv.y * r1.y;
#pragma unroll
        for (int off = 16; off; off >>= 1) {
            s0 += __shfl_xor_sync(0xffffffffu, s0, off);
            s1 += __shfl_xor_sync(0xffffffffu, s1, off);
        }
        if (tc == 0) {
            EC[(size_t)(bm + tr * 2 + 0) * HH + head] = 0.6f * s0;
            EC[(size_t)(bm + tr * 2 + 1) * HH + head] = 0.6f * s1;
        }
    }
}

// ---------------- fused GATv2 attention (m-split partials, f32x2) ----------------
// e[n,m,h] = ecr[n,h] + ecl[m,h] + sum_f c2[f]*|q+g|   (c2 = 0.4*aw)
// BROWS=32, 1024 threads. e-phase: 32 warps = (head, n-quarter), 4 n each.
// agg: c = t&255, n-group = t>>8 (4 groups of 8 n).
__global__ __launch_bounds__(1024, 1)
void gat_kernel(const float* __restrict__ adj, const float* __restrict__ attn_w) {
    extern __shared__ __align__(16) char gat_smem_raw[];
    GatSmem* S = (GatSmem*)gat_smem_raw;

    int t  = threadIdx.x;
    int n0 = blockIdx.x * BROWS;
    int sp = blockIdx.y;
    int mbase = sp * MPS;

    // load queries (as 16B) + coefficient vector + ecr
    {
        ulonglong2* sq2 = (ulonglong2*)S->sq;
#pragma unroll
        for (int j = 0; j < 2; j++) {
            int i = t + j * 1024;                 // 0 .. 2047
            int r = i >> 6, c2 = i & 63;
            sq2[i] = *(const ulonglong2*)(g_gr + (size_t)(n0 + r) * CD + 4 * c2);
        }
    }
    if (t < FF) S->c2s[t] = 0.4f * attn_w[t];
    else if (t >= 64 && t < 64 + BROWS * HH) S->ecr_s[t - 64] = g_ecr[n0 * HH + (t - 64)];

    int em   = t & 31;
    int wrp  = t >> 5;         // 0..31
    int eh   = wrp & 3;        // head
    int nb   = (wrp >> 2) * 4; // n base within block: 0,4,...,28

    // agg mapping
    int ac  = t & 255;         // output column
    int ah  = ac >> 6;         // head for w_t reads
    int nb8 = (t >> 8) * 8;    // n base (0,8,16,24)

    float dsum[4] = {0.f, 0.f, 0.f, 0.f};
    ull accp[4] = {0ULL, 0ULL, 0ULL, 0ULL};   // n-pairs within my 8-n group

    const ulonglong2* qb  = (const ulonglong2*)&S->sq[nb][eh * FF];  // n stride = 64 ulonglong2
    const ulonglong2* c2p = (const ulonglong2*)S->c2s;

    for (int tile = 0; tile < NTILES; tile++) {
        int m0 = mbase + tile * TMm;
        __syncthreads();  // previous agg done before overwriting gl2 / w_t

        // load g_l tile as 16B groups: gl2[h][fp2][m]; plus ecl + adj tiles
#pragma unroll
        for (int j = 0; j < 2; j++) {
            int i = t + j * 1024;                 // 0 .. 2047
            int m = i >> 6, cc2 = i & 63;
            S->gl2[cc2 >> 4][cc2 & 15][m] =
                *(const ulonglong2*)(g_gl + (size_t)(m0 + m) * CD + 4 * cc2);
        }
        if (t < TMm * HH) S->ecl_s[t] = g_ecl[m0 * HH + t];
        else if (t < TMm * HH + TMm * 8) {
            int i = t - TMm * HH;      // 0..255 -> 32 rows x 8 float4
            int row = i >> 3, hf = (i & 7) * 4;
            *(float4*)&S->adj_s[row][hf] =
                *(const float4*)(adj + (size_t)(m0 + row) * NN + n0 + hf);
        }
        __syncthreads();

        // ---- e-phase: e[n0+nb .. +3, m0+em, eh] ----
        {
            ull aB0 = 0, aB1 = 0, aB2 = 0, aB3 = 0;
            const ulonglong2* gp = &S->gl2[eh][0][em];
#pragma unroll
            for (int fp2 = 0; fp2 < FF / 4; fp2++) {
                ulonglong2 c2v = c2p[fp2];
                ulonglong2 g   = gp[fp2 * (TMm + 1)];
                ull x0, x1;
                ulonglong2 qv;
#define EABS(N, ACC) \
                qv = qb[(N) * 64 + fp2]; \
                x0 = add2(qv.x, g.x); x1 = add2(qv.y, g.y); \
                ACC = fma2(c2v.x, x0 & ABSM, ACC); \
                ACC = fma2(c2v.y, x1 & ABSM, ACC);
                EABS(0, aB0) EABS(1, aB1) EABS(2, aB2) EABS(3, aB3)
#undef EABS
            }
            float base = S->ecl_s[em * HH + eh];

            float4 am = *(const float4*)&S->adj_s[em][nb];
            float w0 = (am.x != 0.f) ? __expf(hsum2(aB0) + base + S->ecr_s[(nb + 0) * HH + eh]) : 0.f;
            float w1 = (am.y != 0.f) ? __expf(hsum2(aB1) + base + S->ecr_s[(nb + 1) * HH + eh]) : 0.f;
            float w2 = (am.z != 0.f) ? __expf(hsum2(aB2) + base + S->ecr_s[(nb + 2) * HH + eh]) : 0.f;
            float w3 = (am.w != 0.f) ? __expf(hsum2(aB3) + base + S->ecr_s[(nb + 3) * HH + eh]) : 0.f;
            dsum[0] += w0; dsum[1] += w1; dsum[2] += w2; dsum[3] += w3;
            *(float4*)&S->w_t[em][eh * 32 + nb] = make_float4(w0, w1, w2, w3);
        }
        __syncthreads();

        // ---- aggregation: software-pipelined g prefetch (MLP=8) ----
        const float* grp = g_gr + (size_t)m0 * CD + ac;
        float gpref[8];
#pragma unroll
        for (int j = 0; j < 8; j++) gpref[j] = __ldg(grp + (size_t)j * CD);
#pragma unroll
        for (int ch = 0; ch < 4; ch++) {
            float gcur[8];
#pragma unroll
            for (int j = 0; j < 8; j++) gcur[j] = gpref[j];
            if (ch < 3) {
#pragma unroll
                for (int j = 0; j < 8; j++)
                    gpref[j] = __ldg(grp + (size_t)((ch + 1) * 8 + j) * CD);
            }
#pragma unroll
            for (int j = 0; j < 8; j++) {
                int m = ch * 8 + j;
                ull gv2 = pack2(gcur[j], gcur[j]);
                ulonglong2 wa = *(const ulonglong2*)&S->w_t[m][ah * 32 + nb8];
                ulonglong2 wb = *(const ulonglong2*)&S->w_t[m][ah * 32 + nb8 + 4];
                accp[0] = fma2(wa.x, gv2, accp[0]);
                accp[1] = fma2(wa.y, gv2, accp[1]);
                accp[2] = fma2(wb.x, gv2, accp[2]);
                accp[3] = fma2(wb.y, gv2, accp[3]);
            }
        }
    }

    // reduce dsum over lanes (lanes = m slices) -> partial denominators
    {
#pragma unroll
        for (int off = 16; off; off >>= 1) {
#pragma unroll
            for (int i = 0; i < 4; i++)
                dsum[i] += __shfl_xor_sync(0xffffffffu, dsum[i], off);
        }
        if (em == 0) {
#pragma unroll
            for (int i = 0; i < 4; i++)
                g_pden[((size_t)sp * NN + n0 + nb + i) * HH + eh] = dsum[i];
        }
    }

    // partial numerators (8 n's per thread, column ac)
#pragma unroll
    for (int np = 0; np < 4; np++) {
        float2 v = unpack2(accp[np]);
        g_pacc[((size_t)sp * NN + n0 + nb8 + 2 * np + 0) * CD + ac] = v.x;
        g_pacc[((size_t)sp * NN + n0 + nb8 + 2 * np + 1) * CD + ac] = v.y;
    }
}

// ---------------- combine partials + elu (float4) ----------------
__global__ __launch_bounds__(256)
void combine_kernel(const int* __restrict__ use_elu_p, float* __restrict__ out) {
    int idx = blockIdx.x * 256 + threadIdx.x;        // 0 .. 65535 (float4 slots)
    int n   = idx >> 6;
    int c4  = idx & 63;                              // float4 column
    int h   = c4 >> 4;
    float4 a = make_float4(0.f, 0.f, 0.f, 0.f);
    float  d = 0.f;
#pragma unroll
    for (int sp = 0; sp < NSPLIT; sp++) {
        float4 p = *(const float4*)&g_pacc[((size_t)sp * NN + n) * CD + 4 * c4];
        a.x += p.x; a.y += p.y; a.z += p.z; a.w += p.w;
        d += g_pden[((size_t)sp * NN + n) * HH + h];
    }
    float inv = 1.f / d;
    float4 v = make_float4(a.x * inv, a.y * inv, a.z * inv, a.w * inv);
    if (*use_elu_p) {
        v.x = (v.x > 0.f) ? v.x : expm1f(v.x);
        v.y = (v.y > 0.f) ? v.y : expm1f(v.y);
        v.z = (v.z > 0.f) ? v.z : expm1f(v.z);
        v.w = (v.w > 0.f) ? v.w : expm1f(v.w);
    }
    *(float4*)&out[(size_t)n * CD + 4 * c4] = v;
}

extern "C" void kernel_launch(void* const* d_in, const int* in_sizes, int n_in,
                              void* d_out, int out_size) {
    const float* h    = (const float*)d_in[0];
    const float* nei  = (const float*)d_in[1];
    const float* adj  = (const float*)d_in[2];
    const float* w_l  = (const float*)d_in[3];
    const float* w_r  = (const float*)d_in[4];
    const float* aw   = (const float*)d_in[5];
    const int*   uelu = (const int*)d_in[6];
    float* out = (float*)d_out;

    // idempotent attribute set; capture-safe (not a stream op)
    cudaFuncSetAttribute(gat_kernel,
                         cudaFuncAttributeMaxDynamicSharedMemorySize,
                         (int)sizeof(GatSmem));

    dim3 ggrid(CD / 64, NN / 32, 2);
    gemm_kernel<<<ggrid, 512>>>(h, w_l, nei, w_r, aw);
    dim3 agrid(NN / BROWS, NSPLIT);
    gat_kernel<<<agrid, 1024, sizeof(GatSmem)>>>(adj, aw);
    combine_kernel<<<NN * CD / 4 / 256, 256>>>(uelu, out);
}